// round 15
// baseline (speedup 1.0000x reference)
#include <cuda_runtime.h>
#include <cuda_bf16.h>
#include <stdint.h>

// RZGate, L=12, D=2, J=1.  S = diag(1,-1) => U is DIAGONAL with
//   theta(row) = -0.5 * sum_i a_i * (bit_i(row) ? -1 : +1)   (site 0 = MSB)
//
// TRUE ABI (validated rounds 9-14): __output__ is FLOAT32 = REAL PART of
// the complex reference, out_size == NELEMS:
//   out[row,b] = cos(theta(row)) * x[row,b]        (4 MB in, 4 MB out)
//
// Round-14 post-mortem: __stcs + vector angle loads REGRESSED (L2-hot
// replays; longer prologue) -> reverted. Timed pinned at 6.88 for 5 rounds
// -> harness floor ~1.4us above kernel. This round: single perfectly
// balanced wave — 128 CTAs (<=1 per SM, zero CTA serialization) x 512
// threads x 16 floats/thread, 4 independent LDG.128 per thread (64
// outstanding loads/SM), one MUFU cos per thread.

#define LQ      12
#define NROWS   4096
#define NBATCH  256
#define NELEMS  (NROWS * NBATCH)   // 1,048,576

// ---------------------------------------------------------------------------
// FAST kernel: 128 blocks x 512 threads, 16 consecutive floats per thread
// (16 threads per 256-float row -> row uniform across the thread's span).
// ---------------------------------------------------------------------------
__global__ void __launch_bounds__(512)
rz_real(const float* __restrict__ x,
        const float* __restrict__ ang,
        float*       __restrict__ out,
        int xv4, int ov4)
{
    const int tid = blockIdx.x * blockDim.x + threadIdx.x;   // 0..65535
    const int e0  = tid * 16;
    const int row = tid >> 4;          // 16 threads per row

    // ---- front-batched loads: 4 independent LDG.128 (MLP = 4) ----
    float v[16];
    if (xv4) {
        const float4* __restrict__ x4 = (const float4*)x;
        const float4 a = x4[4 * tid + 0];
        const float4 b = x4[4 * tid + 1];
        const float4 c = x4[4 * tid + 2];
        const float4 d = x4[4 * tid + 3];
        v[0]  = a.x; v[1]  = a.y; v[2]  = a.z; v[3]  = a.w;
        v[4]  = b.x; v[5]  = b.y; v[6]  = b.z; v[7]  = b.w;
        v[8]  = c.x; v[9]  = c.y; v[10] = c.z; v[11] = c.w;
        v[12] = d.x; v[13] = d.y; v[14] = d.z; v[15] = d.w;
    } else {
#pragma unroll
        for (int j = 0; j < 16; ++j) v[j] = __ldg(&x[e0 + j]);
    }

    // ---- per-thread phase (runs under the load latency) ----
    float th = 0.0f;
#pragma unroll
    for (int i = 0; i < LQ; ++i) {
        const float a   = __ldg(&ang[i]);
        const int   bit = (row >> (LQ - 1 - i)) & 1;
        th += bit ? -a : a;
    }
    const float cs = __cosf(0.5f * th);   // cos even; MUFU (tol 1e-3 >> err)

    // ---- multiply + store (4 STG.128) ----
    if (ov4) {
        float4* __restrict__ o4 = (float4*)(out + e0);
        o4[0] = make_float4(cs * v[0],  cs * v[1],  cs * v[2],  cs * v[3]);
        o4[1] = make_float4(cs * v[4],  cs * v[5],  cs * v[6],  cs * v[7]);
        o4[2] = make_float4(cs * v[8],  cs * v[9],  cs * v[10], cs * v[11]);
        o4[3] = make_float4(cs * v[12], cs * v[13], cs * v[14], cs * v[15]);
    } else {
#pragma unroll
        for (int j = 0; j < 16; ++j) out[e0 + j] = cs * v[j];
    }
}

// ---------------------------------------------------------------------------
// SAFE fallback: all-scalar, dtype-probing, bounds-clamped (proven passing).
// ---------------------------------------------------------------------------
__global__ void __launch_bounds__(256)
rz_safe(const void* __restrict__ xraw, int x_elems,
        const void* __restrict__ araw,
        float* __restrict__ outf, int n_out_floats,
        int interleaved, int x_hint, int a_hint)
{
    __shared__ float2 s_phase[4];
    __shared__ int    s_xbf;
    const int t = threadIdx.x;

    if (t == 0) {
        int xbf = x_hint;
        if (xbf < 0) {
            const unsigned short* h = (const unsigned short*)xraw;
            int match = 0;
            for (int i = 0; i < 32; ++i) {
                const int e = (h[2 * i] >> 7) & 0xFF;
                if (e >= 117 && e <= 132) ++match;
            }
            xbf = (match >= 24) ? 1 : 0;
        }
        s_xbf = xbf;
    }
    __syncthreads();
    const int xbf = s_xbf;

    if (t < 4) {
        const int abf = (a_hint >= 0) ? a_hint : xbf;
        const int row = 4 * blockIdx.x + t;
        float th = 0.0f;
#pragma unroll
        for (int i = 0; i < LQ; ++i) {
            float a;
            if (abf) a = __bfloat162float(((const __nv_bfloat16*)araw)[i]);
            else     a = ((const float*)araw)[i];
            const int bit = (row >> (LQ - 1 - i)) & 1;
            th = fmaf(a, bit ? -1.0f : 1.0f, th);
        }
        th *= -0.5f;
        float sc, cc;
        sincosf(th, &sc, &cc);
        s_phase[t] = make_float2(cc, sc);
    }
    __syncthreads();

    const int    e0 = blockIdx.x * 1024 + 4 * t;
    const float2 p  = s_phase[t >> 6];

    float v[4];
#pragma unroll
    for (int j = 0; j < 4; ++j) {
        const int e = e0 + j;
        v[j] = 0.0f;
        if (e < x_elems) {
            if (xbf) v[j] = __bfloat162float(((const __nv_bfloat16*)xraw)[e]);
            else     v[j] = ((const float*)xraw)[e];
        }
    }
    if (interleaved) {
#pragma unroll
        for (int j = 0; j < 4; ++j) {
            const int idx = 2 * (e0 + j);
            if (idx + 1 < n_out_floats) {
                outf[idx]     = p.x * v[j];
                outf[idx + 1] = p.y * v[j];
            }
        }
    } else {
#pragma unroll
        for (int j = 0; j < 4; ++j)
            if (e0 + j < n_out_floats) outf[e0 + j] = p.x * v[j];
    }
}

extern "C" void kernel_launch(void* const* d_in, const int* in_sizes, int n_in,
                              void* d_out, int out_size)
{
    // Identify inputs: x = largest, angle = sized 12/24/48.
    int ix = -1, ia = -1;
    for (int i = 0; i < n_in; ++i) {
        const int sz = in_sizes[i];
        if (sz == 12 || sz == 24 || sz == 48) ia = i;
        else if (ix < 0 || sz > in_sizes[ix]) ix = i;
    }
    if (ix < 0) return;
    if (ia < 0) ia = (n_in > 1) ? 1 : ix;

    const void* x = d_in[ix];
    const void* a = d_in[ia];

    int a_hint = -1;
    if (in_sizes[ia] == 48) a_hint = 0;
    else if (in_sizes[ia] == 24) a_hint = 1;
    int x_hint = (in_sizes[ix] == 4 * NELEMS) ? 0 : -1;

    int x_elems = in_sizes[ix];
    if (x_elems > NELEMS) x_elems = NELEMS;

    int interleaved, n_out_floats;
    if (out_size >= 2 * NELEMS)  { interleaved = 1; n_out_floats = 2 * NELEMS; }
    else if (out_size >= NELEMS) { interleaved = 0; n_out_floats = NELEMS; }
    else { interleaved = 0; n_out_floats = out_size > 0 ? out_size : 0; }

    const bool fast_ok = !interleaved && n_out_floats == NELEMS &&
                         x_elems == NELEMS && a_hint != 1;

    if (fast_ok) {
        const int xv4 = (((uintptr_t)x     & 15u) == 0);
        const int ov4 = (((uintptr_t)d_out & 15u) == 0);
        // 128 CTAs x 512 threads x 16 floats = NELEMS exactly; one balanced wave.
        rz_real<<<NELEMS / 8192, 512>>>((const float*)x, (const float*)a,
                                        (float*)d_out, xv4, ov4);
    } else {
        rz_safe<<<NELEMS / 1024, 256>>>(x, x_elems, a,
                                        (float*)d_out, n_out_floats,
                                        interleaved, x_hint, a_hint);
    }
}

// round 16
// speedup vs baseline: 1.1406x; 1.1406x over previous
#include <cuda_runtime.h>
#include <cuda_bf16.h>
#include <stdint.h>

// RZGate, L=12, D=2, J=1.  S = diag(1,-1) => U is DIAGONAL with
//   theta(row) = -0.5 * sum_i a_i * (bit_i(row) ? -1 : +1)   (site 0 = MSB)
//
// TRUE ABI (validated rounds 9-15): __output__ is FLOAT32 = REAL PART of
// the complex reference, out_size == NELEMS:
//   out[row,b] = cos(theta(row)) * x[row,b]        (4 MB in, 4 MB out)
//
// Config sweep result (rounds 10-15): 512 CTAs x 256 thr, 8 floats/thread,
// per-thread MUFU cos, normal stores = measured optimum (ncu 5.31us).
// R14 (__stcs) and R15 (128x512 single wave) both regressed -> reverted.
// This round: R13 + sign-bit-XOR phase accumulation (LOP3+FADD, no
// predicated select) + all loads front-batched.

#define LQ      12
#define NROWS   4096
#define NBATCH  256
#define NELEMS  (NROWS * NBATCH)   // 1,048,576

// ---------------------------------------------------------------------------
// FAST kernel: 512 blocks x 256 threads, 8 consecutive floats per thread
// (32 threads per 256-float row -> row uniform across the thread's span).
// ---------------------------------------------------------------------------
__global__ void __launch_bounds__(256)
rz_real(const float* __restrict__ x,
        const float* __restrict__ ang,
        float*       __restrict__ out,
        int xv4, int ov4)
{
    const int tid = blockIdx.x * blockDim.x + threadIdx.x;
    const int e0  = tid * 8;
    const int row = tid >> 5;          // 32 threads per row

    // ---- front-batch ALL loads: 2 independent LDG.128 + 12 L1-hit LDGs ----
    float v[8];
    if (xv4) {
        const float4* __restrict__ x4 = (const float4*)x;
        const float4 a = x4[2 * tid + 0];
        const float4 b = x4[2 * tid + 1];
        v[0] = a.x; v[1] = a.y; v[2] = a.z; v[3] = a.w;
        v[4] = b.x; v[5] = b.y; v[6] = b.z; v[7] = b.w;
    } else {
#pragma unroll
        for (int j = 0; j < 8; ++j) v[j] = __ldg(&x[e0 + j]);
    }

    float aa[LQ];
#pragma unroll
    for (int i = 0; i < LQ; ++i) aa[i] = __ldg(&ang[i]);

    // ---- per-thread phase: sign via IEEE sign-bit XOR (LOP3 + FADD) ----
    float th = 0.0f;
#pragma unroll
    for (int i = 0; i < LQ; ++i) {
        const unsigned sign = ((unsigned)(row >> (LQ - 1 - i)) & 1u) << 31;
        th += __uint_as_float(__float_as_uint(aa[i]) ^ sign);
    }
    // cos is even: cos(-0.5*th) == cos(0.5*th). MUFU (tol 1e-3 >> ~1e-6 err).
    const float cs = __cosf(0.5f * th);

    // ---- multiply + store (2 STG.128) ----
    if (ov4) {
        float4* __restrict__ o4 = (float4*)(out + e0);
        o4[0] = make_float4(cs * v[0], cs * v[1], cs * v[2], cs * v[3]);
        o4[1] = make_float4(cs * v[4], cs * v[5], cs * v[6], cs * v[7]);
    } else {
#pragma unroll
        for (int j = 0; j < 8; ++j) out[e0 + j] = cs * v[j];
    }
}

// ---------------------------------------------------------------------------
// SAFE fallback: all-scalar, dtype-probing, bounds-clamped (proven passing).
// ---------------------------------------------------------------------------
__global__ void __launch_bounds__(256)
rz_safe(const void* __restrict__ xraw, int x_elems,
        const void* __restrict__ araw,
        float* __restrict__ outf, int n_out_floats,
        int interleaved, int x_hint, int a_hint)
{
    __shared__ float2 s_phase[4];
    __shared__ int    s_xbf;
    const int t = threadIdx.x;

    if (t == 0) {
        int xbf = x_hint;
        if (xbf < 0) {
            const unsigned short* h = (const unsigned short*)xraw;
            int match = 0;
            for (int i = 0; i < 32; ++i) {
                const int e = (h[2 * i] >> 7) & 0xFF;
                if (e >= 117 && e <= 132) ++match;
            }
            xbf = (match >= 24) ? 1 : 0;
        }
        s_xbf = xbf;
    }
    __syncthreads();
    const int xbf = s_xbf;

    if (t < 4) {
        const int abf = (a_hint >= 0) ? a_hint : xbf;
        const int row = 4 * blockIdx.x + t;
        float th = 0.0f;
#pragma unroll
        for (int i = 0; i < LQ; ++i) {
            float a;
            if (abf) a = __bfloat162float(((const __nv_bfloat16*)araw)[i]);
            else     a = ((const float*)araw)[i];
            const int bit = (row >> (LQ - 1 - i)) & 1;
            th = fmaf(a, bit ? -1.0f : 1.0f, th);
        }
        th *= -0.5f;
        float sc, cc;
        sincosf(th, &sc, &cc);
        s_phase[t] = make_float2(cc, sc);
    }
    __syncthreads();

    const int    e0 = blockIdx.x * 1024 + 4 * t;
    const float2 p  = s_phase[t >> 6];

    float v[4];
#pragma unroll
    for (int j = 0; j < 4; ++j) {
        const int e = e0 + j;
        v[j] = 0.0f;
        if (e < x_elems) {
            if (xbf) v[j] = __bfloat162float(((const __nv_bfloat16*)xraw)[e]);
            else     v[j] = ((const float*)xraw)[e];
        }
    }
    if (interleaved) {
#pragma unroll
        for (int j = 0; j < 4; ++j) {
            const int idx = 2 * (e0 + j);
            if (idx + 1 < n_out_floats) {
                outf[idx]     = p.x * v[j];
                outf[idx + 1] = p.y * v[j];
            }
        }
    } else {
#pragma unroll
        for (int j = 0; j < 4; ++j)
            if (e0 + j < n_out_floats) outf[e0 + j] = p.x * v[j];
    }
}

extern "C" void kernel_launch(void* const* d_in, const int* in_sizes, int n_in,
                              void* d_out, int out_size)
{
    // Identify inputs: x = largest, angle = sized 12/24/48.
    int ix = -1, ia = -1;
    for (int i = 0; i < n_in; ++i) {
        const int sz = in_sizes[i];
        if (sz == 12 || sz == 24 || sz == 48) ia = i;
        else if (ix < 0 || sz > in_sizes[ix]) ix = i;
    }
    if (ix < 0) return;
    if (ia < 0) ia = (n_in > 1) ? 1 : ix;

    const void* x = d_in[ix];
    const void* a = d_in[ia];

    int a_hint = -1;
    if (in_sizes[ia] == 48) a_hint = 0;
    else if (in_sizes[ia] == 24) a_hint = 1;
    int x_hint = (in_sizes[ix] == 4 * NELEMS) ? 0 : -1;

    int x_elems = in_sizes[ix];
    if (x_elems > NELEMS) x_elems = NELEMS;

    int interleaved, n_out_floats;
    if (out_size >= 2 * NELEMS)  { interleaved = 1; n_out_floats = 2 * NELEMS; }
    else if (out_size >= NELEMS) { interleaved = 0; n_out_floats = NELEMS; }
    else { interleaved = 0; n_out_floats = out_size > 0 ? out_size : 0; }

    const bool fast_ok = !interleaved && n_out_floats == NELEMS &&
                         x_elems == NELEMS && a_hint != 1;

    if (fast_ok) {
        const int xv4 = (((uintptr_t)x     & 15u) == 0);
        const int ov4 = (((uintptr_t)d_out & 15u) == 0);
        rz_real<<<NELEMS / 2048, 256>>>((const float*)x, (const float*)a,
                                        (float*)d_out, xv4, ov4);
    } else {
        rz_safe<<<NELEMS / 1024, 256>>>(x, x_elems, a,
                                        (float*)d_out, n_out_floats,
                                        interleaved, x_hint, a_hint);
    }
}